// round 7
// baseline (speedup 1.0000x reference)
#include <cuda_runtime.h>

#define L 2048
#define B 32
#define B2 16             // batch half
#define H 1024
#define H4 (H / 4)
#define GCH 64            // g-chunks for K1 partials
#define GSZ (H / GCH)     // 16 g per chunk
#define LTILES 64
#define LPT (L / LTILES)  // 32 l-positions per K2 block

// Scratch (allocation-free rule: __device__ globals)
__device__ float g_vpart[GCH][B][H];     // 8 MB partial v (L2-resident)
__device__ float g_vhalf[2][B][H];       // 256 KB two-chunk-half reduced v
__device__ float g_energy[B][L];         // 256 KB energies
__device__ unsigned g_maxu[B];           // monotone-encoded per-b max

// monotone float->uint encoding: order-preserving for all floats
__device__ __forceinline__ unsigned enc_f(float x) {
    unsigned u = __float_as_uint(x);
    return (x >= 0.f) ? (u | 0x80000000u) : ~u;
}
__device__ __forceinline__ float dec_f(unsigned e) {
    return (e & 0x80000000u) ? __uint_as_float(e ^ 0x80000000u)
                             : __uint_as_float(~e);
}

// ---------------------------------------------------------------------------
// K1 (per b-half): vpart[gc][b][h] = sum_{g in chunk} hidden[b,g]*W[g,h]
// grid (8, 64) = 512 blocks; block 256 = 32 h-quads x 8 groups x 2 b.
// Explicit 8-deep load batches, 16 LDG.128/thread.
// ---------------------------------------------------------------------------
__global__ void k1_proj(const float* __restrict__ hidden,
                        const float* __restrict__ W, int b0) {
    const int tid = threadIdx.x;
    const int hq  = tid & 31;
    const int bq  = tid >> 5;                    // 0..7 -> 2 b's each
    const int hq_glob = blockIdx.x * 32 + hq;
    const int g0  = blockIdx.y * GSZ;

    __shared__ float hsh[B2][GSZ];               // 1 KB hidden chunk
    if (tid < B2 * GSZ / 4) {                    // 64 float4 loads
        const int bb = tid >> 2, g4 = tid & 3;
        ((float4*)hsh[bb])[g4] =
            ((const float4*)hidden)[(size_t)(b0 + bb) * H4 + (g0 >> 2) + g4];
    }
    __syncthreads();

    float4 acc[2];
    acc[0] = make_float4(0.f, 0.f, 0.f, 0.f);
    acc[1] = make_float4(0.f, 0.f, 0.f, 0.f);

    const float4* __restrict__ W4 = (const float4*)W;
    #pragma unroll
    for (int t = 0; t < GSZ / 8; t++) {
        float4 w[8];                             // 8 loads in flight
        #pragma unroll
        for (int i = 0; i < 8; i++)
            w[i] = W4[(size_t)(g0 + t * 8 + i) * H4 + hq_glob];
        #pragma unroll
        for (int i = 0; i < 8; i++) {
            #pragma unroll
            for (int j = 0; j < 2; j++) {
                const float hv = hsh[bq * 2 + j][t * 8 + i];
                acc[j].x += w[i].x * hv; acc[j].y += w[i].y * hv;
                acc[j].z += w[i].z * hv; acc[j].w += w[i].w * hv;
            }
        }
    }

    #pragma unroll
    for (int j = 0; j < 2; j++)
        *(float4*)&g_vpart[blockIdx.y][b0 + bq * 2 + j][hq_glob * 4] = acc[j];
}

// ---------------------------------------------------------------------------
// K1b (per b-half): g_vhalf[s][b][h] = sum_{p in chunk-half s} vpart[p][b][h]
// 8192 threads (32 blocks x 256), 32 L2 loads each. Also inits g_maxu.
// ---------------------------------------------------------------------------
__global__ void k1b_reduce(int b0) {
    if (blockIdx.x == 0 && threadIdx.x < B2)
        g_maxu[b0 + threadIdx.x] = 0u;           // encoded -inf sentinel

    const int t  = blockIdx.x * 256 + threadIdx.x;   // 0..8191
    const int ch = t >> 12;                          // chunk-half 0..1
    const int idx = t & 4095;                        // float4 idx in half
    const int bl = idx / H4;                         // 0..15
    const int h4 = idx % H4;
    const int p0 = ch * (GCH / 2);
    float4 s = make_float4(0.f, 0.f, 0.f, 0.f);
    #pragma unroll 8
    for (int p = 0; p < GCH / 2; p++) {
        const float4 v = *(const float4*)&g_vpart[p0 + p][b0 + bl][h4 * 4];
        s.x += v.x; s.y += v.y; s.z += v.z; s.w += v.w;
    }
    *(float4*)&g_vhalf[ch][b0 + bl][h4 * 4] = s;
}

// ---------------------------------------------------------------------------
// K2 (per b-half): energies[b][l] = dot(enc[l,b,:], v[b,:])
// grid (LTILES=64, 16), block 256 (8 warps x 4 l's). Maintains g_maxu[b].
// ---------------------------------------------------------------------------
__global__ void k2_energy(const float* __restrict__ enc, int b0) {
    const int b  = b0 + blockIdx.y;
    const int l0 = blockIdx.x * LPT;
    const int tid = threadIdx.x;

    __shared__ float4 vsh[H4];   // 4 KB
    {
        const float4 v0 = *(const float4*)&g_vhalf[0][b][tid * 4];
        const float4 v1 = *(const float4*)&g_vhalf[1][b][tid * 4];
        vsh[tid] = make_float4(v0.x + v1.x, v0.y + v1.y, v0.z + v1.z, v0.w + v1.w);
    }
    __syncthreads();

    const int warp = tid >> 5, lane = tid & 31;
    const float4* __restrict__ enc4 = (const float4*)enc;

    const int la = l0 + warp * 4;
    size_t base[4];
    #pragma unroll
    for (int j = 0; j < 4; j++)
        base[j] = ((size_t)(la + j) * B + b) * H4;

    float a0 = 0.f, a1 = 0.f, a2 = 0.f, a3 = 0.f;
    #pragma unroll
    for (int k = 0; k < 8; k++) {
        const float4 v  = vsh[k * 32 + lane];
        const float4 e0 = __ldcs(&enc4[base[0] + k * 32 + lane]);
        const float4 e1 = __ldcs(&enc4[base[1] + k * 32 + lane]);
        const float4 e2 = __ldcs(&enc4[base[2] + k * 32 + lane]);
        const float4 e3 = __ldcs(&enc4[base[3] + k * 32 + lane]);
        a0 += e0.x * v.x + e0.y * v.y + e0.z * v.z + e0.w * v.w;
        a1 += e1.x * v.x + e1.y * v.y + e1.z * v.z + e1.w * v.w;
        a2 += e2.x * v.x + e2.y * v.y + e2.z * v.z + e2.w * v.w;
        a3 += e3.x * v.x + e3.y * v.y + e3.z * v.z + e3.w * v.w;
    }
    #pragma unroll
    for (int s = 16; s; s >>= 1) {
        a0 += __shfl_down_sync(0xffffffffu, a0, s);
        a1 += __shfl_down_sync(0xffffffffu, a1, s);
        a2 += __shfl_down_sync(0xffffffffu, a2, s);
        a3 += __shfl_down_sync(0xffffffffu, a3, s);
    }
    if (lane == 0) {
        g_energy[b][la + 0] = a0;
        g_energy[b][la + 1] = a1;
        g_energy[b][la + 2] = a2;
        g_energy[b][la + 3] = a3;
        const float m = fmaxf(fmaxf(a0, a1), fmaxf(a2, a3));
        atomicMax(&g_maxu[b], enc_f(m));   // raw max; softmax shift-invariant
    }
}

// ---------------------------------------------------------------------------
// K3: masked softmax per b. grid B, block 512, float4/thread.
// Max precomputed by K2 -> only the sum reduction remains.
// ---------------------------------------------------------------------------
__global__ void k3_softmax(const int* __restrict__ lengths,
                           float* __restrict__ out) {
    const int b   = blockIdx.x;
    const int len = lengths[b];
    const int tid = threadIdx.x;
    const int l0  = tid * 4;

    const float4 e = ((const float4*)&g_energy[b][0])[tid];
    const float mx = dec_f(g_maxu[b]);

    float4 x;
    x.x = (l0 + 0 < len) ? expf(e.x - mx) : 0.f;
    x.y = (l0 + 1 < len) ? expf(e.y - mx) : 0.f;
    x.z = (l0 + 2 < len) ? expf(e.z - mx) : 0.f;
    x.w = (l0 + 3 < len) ? expf(e.w - mx) : 0.f;

    __shared__ float red_s[16];
    float sum = x.x + x.y + x.z + x.w;
    #pragma unroll
    for (int s = 16; s; s >>= 1)
        sum += __shfl_xor_sync(0xffffffffu, sum, s);
    if ((tid & 31) == 0) red_s[tid >> 5] = sum;
    __syncthreads();
    if (tid < 32) {
        float m = (tid < 16) ? red_s[tid] : 0.f;
        #pragma unroll
        for (int s = 8; s; s >>= 1)
            m += __shfl_xor_sync(0xffffffffu, m, s);
        if (tid == 0) red_s[0] = m;
    }
    __syncthreads();
    const float inv = 1.f / red_s[0];

    x.x *= inv; x.y *= inv; x.z *= inv; x.w *= inv;
    ((float4*)(out + (size_t)b * L))[tid] = x;
}

// ---------------------------------------------------------------------------
// Pipeline: b-half 0 proj -> fork{ K2(half0) } while main does b-half 1 proj
// -> K2(half1) on main, join, softmax.
// ---------------------------------------------------------------------------
extern "C" void kernel_launch(void* const* d_in, const int* in_sizes, int n_in,
                              void* d_out, int out_size) {
    const float* hidden  = (const float*)d_in[0];   // [1,B,H]
    const float* enc     = (const float*)d_in[1];   // [L,B,H]
    const float* W       = (const float*)d_in[2];   // [H,H]
    // d_in[3] = bias — provably cancels in softmax, unused
    const int*   lengths = (const int*)d_in[4];     // [B]
    float* out = (float*)d_out;                     // [B,1,L]

    cudaStream_t sm = 0;   // capture-origin (legacy) stream
    cudaStream_t s2;
    cudaEvent_t evF, evJ;
    cudaStreamCreateWithFlags(&s2, cudaStreamNonBlocking);
    cudaEventCreateWithFlags(&evF, cudaEventDisableTiming);
    cudaEventCreateWithFlags(&evJ, cudaEventDisableTiming);

    // b-half 0 projection on main
    k1_proj<<<dim3(8, GCH), 256, 0, sm>>>(hidden, W, 0);
    k1b_reduce<<<32, 256, 0, sm>>>(0);

    // fork: K2 for b-half 0 on side stream
    cudaEventRecord(evF, sm);
    cudaStreamWaitEvent(s2, evF, 0);
    k2_energy<<<dim3(LTILES, B2), 256, 0, s2>>>(enc, 0);
    cudaEventRecord(evJ, s2);

    // main: b-half 1 projection (concurrent with K2 half 0), then its K2
    k1_proj<<<dim3(8, GCH), 256, 0, sm>>>(hidden, W, B2);
    k1b_reduce<<<32, 256, 0, sm>>>(B2);
    k2_energy<<<dim3(LTILES, B2), 256, 0, sm>>>(enc, B2);

    // join + softmax
    cudaStreamWaitEvent(sm, evJ, 0);
    k3_softmax<<<B, 512, 0, sm>>>(lengths, out);

    // destroy handles only outside capture (leaks once during the capture call)
    cudaStreamCaptureStatus st = cudaStreamCaptureStatusNone;
    cudaStreamIsCapturing(sm, &st);
    if (st == cudaStreamCaptureStatusNone) {
        cudaStreamDestroy(s2);
        cudaEventDestroy(evF);
        cudaEventDestroy(evJ);
    }
}

// round 8
// speedup vs baseline: 1.1757x; 1.1757x over previous
#include <cuda_runtime.h>

#define L 2048
#define B 32
#define H 1024
#define H4 (H / 4)
#define GCH 64            // g-chunks for K1 partials
#define GSZ (H / GCH)     // 16 g per chunk
#define LTILES 64
#define LPT (L / LTILES)  // 32 l-positions per K2 block

// Scratch (allocation-free rule: __device__ globals)
__device__ float g_vpart[GCH][B][H];     // 8 MB partial v (L2-resident)
__device__ float g_vhalf[2][B][H];       // 256 KB two-chunk-half reduced v
__device__ float g_energy[B][L];         // 256 KB energies
__device__ unsigned g_maxu[B];           // monotone-encoded per-b max

// monotone float->uint encoding: order-preserving for all floats
__device__ __forceinline__ unsigned enc_f(float x) {
    unsigned u = __float_as_uint(x);
    return (x >= 0.f) ? (u | 0x80000000u) : ~u;
}
__device__ __forceinline__ float dec_f(unsigned e) {
    return (e & 0x80000000u) ? __uint_as_float(e ^ 0x80000000u)
                             : __uint_as_float(~e);
}

// ---------------------------------------------------------------------------
// K1: vpart[gc][b][h] = sum_{g in chunk} hidden[b,g]*W[g,h]
// grid (8, 64) = 512 blocks; block 256 = 32 h-quads x 8 b-quads (4 b each).
// __launch_bounds__(256,2): 128-reg budget so the FULL 16-deep float4 batch
// stays register-resident (R7 showed 36 regs => ptxas collapsed MLP to ~2).
// Each W element hits DRAM exactly once (4 MB total).
// ---------------------------------------------------------------------------
__global__ void __launch_bounds__(256, 2)
k1_proj(const float* __restrict__ hidden, const float* __restrict__ W) {
    const int tid = threadIdx.x;
    const int hq  = tid & 31;
    const int bq  = tid >> 5;                    // 0..7 -> b in [bq*4, bq*4+4)
    const int hq_glob = blockIdx.x * 32 + hq;
    const int g0  = blockIdx.y * GSZ;
    const int b0  = bq * 4;

    __shared__ float hsh[B][GSZ];                // 2 KB hidden chunk
    if (tid < B * GSZ / 4) {                     // 128 float4 loads
        const int bb = tid >> 2, g4 = tid & 3;
        ((float4*)hsh[bb])[g4] =
            ((const float4*)hidden)[(size_t)bb * H4 + (g0 >> 2) + g4];
    }
    __syncthreads();

    const float4* __restrict__ W4 = (const float4*)W;

    float4 w[GSZ];                               // 16 loads in flight (64 regs)
    #pragma unroll
    for (int i = 0; i < GSZ; i++)
        w[i] = W4[(size_t)(g0 + i) * H4 + hq_glob];

    float4 acc[4];
    #pragma unroll
    for (int j = 0; j < 4; j++) acc[j] = make_float4(0.f, 0.f, 0.f, 0.f);

    #pragma unroll
    for (int i = 0; i < GSZ; i++) {
        #pragma unroll
        for (int j = 0; j < 4; j++) {
            const float hv = hsh[b0 + j][i];     // smem broadcast
            acc[j].x += w[i].x * hv; acc[j].y += w[i].y * hv;
            acc[j].z += w[i].z * hv; acc[j].w += w[i].w * hv;
        }
    }

    #pragma unroll
    for (int j = 0; j < 4; j++)
        *(float4*)&g_vpart[blockIdx.y][b0 + j][hq_glob * 4] = acc[j];
}

// ---------------------------------------------------------------------------
// K1b: g_vhalf[s][b][h] = sum_{p in chunk-half s} vpart[p][b][h]
// 16384 threads (64 blocks x 256); 32 L2 loads each, 8-deep batches.
// Also inits g_maxu (stream-ordered before K2, reset every replay).
// ---------------------------------------------------------------------------
__global__ void __launch_bounds__(256, 4) k1b_reduce() {
    if (blockIdx.x == 0 && threadIdx.x < B)
        g_maxu[threadIdx.x] = 0u;                // encoded -inf sentinel

    const int t    = blockIdx.x * 256 + threadIdx.x;   // 0..16383
    const int half = t >> 13;                          // chunk-half 0..1
    const int idx  = t & 8191;                         // float4 idx
    const int b  = idx / H4;
    const int h4 = idx % H4;
    const int p0 = half * (GCH / 2);

    float4 s = make_float4(0.f, 0.f, 0.f, 0.f);
    #pragma unroll
    for (int tt = 0; tt < GCH / 2 / 8; tt++) {
        float4 v[8];
        #pragma unroll
        for (int i = 0; i < 8; i++)
            v[i] = *(const float4*)&g_vpart[p0 + tt * 8 + i][b][h4 * 4];
        #pragma unroll
        for (int i = 0; i < 8; i++) {
            s.x += v[i].x; s.y += v[i].y; s.z += v[i].z; s.w += v[i].w;
        }
    }
    *(float4*)&g_vhalf[half][b][h4 * 4] = s;
}

// ---------------------------------------------------------------------------
// K2: energies[b][l] = dot(enc[l,b,:], v[b,:])
// grid (LTILES=64, B) = 2048 blocks, block 256 (8 warps x 4 l's each).
// At DRAM roofline. Maintains g_maxu[b] so K3 skips its max reduction.
// ---------------------------------------------------------------------------
__global__ void k2_energy(const float* __restrict__ enc) {
    const int b  = blockIdx.y;
    const int l0 = blockIdx.x * LPT;
    const int tid = threadIdx.x;

    __shared__ float4 vsh[H4];   // 4 KB
    {
        const float4 v0 = *(const float4*)&g_vhalf[0][b][tid * 4];
        const float4 v1 = *(const float4*)&g_vhalf[1][b][tid * 4];
        vsh[tid] = make_float4(v0.x + v1.x, v0.y + v1.y, v0.z + v1.z, v0.w + v1.w);
    }
    __syncthreads();

    const int warp = tid >> 5, lane = tid & 31;
    const float4* __restrict__ enc4 = (const float4*)enc;

    const int la = l0 + warp * 4;
    size_t base[4];
    #pragma unroll
    for (int j = 0; j < 4; j++)
        base[j] = ((size_t)(la + j) * B + b) * H4;

    float a0 = 0.f, a1 = 0.f, a2 = 0.f, a3 = 0.f;
    #pragma unroll
    for (int k = 0; k < 8; k++) {
        const float4 v  = vsh[k * 32 + lane];
        const float4 e0 = __ldcs(&enc4[base[0] + k * 32 + lane]);
        const float4 e1 = __ldcs(&enc4[base[1] + k * 32 + lane]);
        const float4 e2 = __ldcs(&enc4[base[2] + k * 32 + lane]);
        const float4 e3 = __ldcs(&enc4[base[3] + k * 32 + lane]);
        a0 += e0.x * v.x + e0.y * v.y + e0.z * v.z + e0.w * v.w;
        a1 += e1.x * v.x + e1.y * v.y + e1.z * v.z + e1.w * v.w;
        a2 += e2.x * v.x + e2.y * v.y + e2.z * v.z + e2.w * v.w;
        a3 += e3.x * v.x + e3.y * v.y + e3.z * v.z + e3.w * v.w;
    }
    #pragma unroll
    for (int s = 16; s; s >>= 1) {
        a0 += __shfl_down_sync(0xffffffffu, a0, s);
        a1 += __shfl_down_sync(0xffffffffu, a1, s);
        a2 += __shfl_down_sync(0xffffffffu, a2, s);
        a3 += __shfl_down_sync(0xffffffffu, a3, s);
    }
    if (lane == 0) {
        g_energy[b][la + 0] = a0;
        g_energy[b][la + 1] = a1;
        g_energy[b][la + 2] = a2;
        g_energy[b][la + 3] = a3;
        const float m = fmaxf(fmaxf(a0, a1), fmaxf(a2, a3));
        atomicMax(&g_maxu[b], enc_f(m));   // raw max; softmax shift-invariant
    }
}

// ---------------------------------------------------------------------------
// K3: masked softmax per b. grid B, block 512, float4/thread.
// Max precomputed by K2 -> only the sum reduction remains.
// ---------------------------------------------------------------------------
__global__ void k3_softmax(const int* __restrict__ lengths,
                           float* __restrict__ out) {
    const int b   = blockIdx.x;
    const int len = lengths[b];
    const int tid = threadIdx.x;
    const int l0  = tid * 4;

    const float4 e = ((const float4*)&g_energy[b][0])[tid];
    const float mx = dec_f(g_maxu[b]);

    float4 x;
    x.x = (l0 + 0 < len) ? expf(e.x - mx) : 0.f;
    x.y = (l0 + 1 < len) ? expf(e.y - mx) : 0.f;
    x.z = (l0 + 2 < len) ? expf(e.z - mx) : 0.f;
    x.w = (l0 + 3 < len) ? expf(e.w - mx) : 0.f;

    __shared__ float red_s[16];
    float sum = x.x + x.y + x.z + x.w;
    #pragma unroll
    for (int s = 16; s; s >>= 1)
        sum += __shfl_xor_sync(0xffffffffu, sum, s);
    if ((tid & 31) == 0) red_s[tid >> 5] = sum;
    __syncthreads();
    if (tid < 32) {
        float m = (tid < 16) ? red_s[tid] : 0.f;
        #pragma unroll
        for (int s = 8; s; s >>= 1)
            m += __shfl_xor_sync(0xffffffffu, m, s);
        if (tid == 0) red_s[0] = m;
    }
    __syncthreads();
    const float inv = 1.f / red_s[0];

    x.x *= inv; x.y *= inv; x.z *= inv; x.w *= inv;
    ((float4*)(out + (size_t)b * L))[tid] = x;
}

// ---------------------------------------------------------------------------
extern "C" void kernel_launch(void* const* d_in, const int* in_sizes, int n_in,
                              void* d_out, int out_size) {
    const float* hidden  = (const float*)d_in[0];   // [1,B,H]
    const float* enc     = (const float*)d_in[1];   // [L,B,H]
    const float* W       = (const float*)d_in[2];   // [H,H]
    // d_in[3] = bias — provably cancels in softmax, unused
    const int*   lengths = (const int*)d_in[4];     // [B]
    float* out = (float*)d_out;                     // [B,1,L]

    k1_proj<<<dim3(8, GCH), 256>>>(hidden, W);
    k1b_reduce<<<64, 256>>>();
    k2_energy<<<dim3(LTILES, B), 256>>>(enc);
    k3_softmax<<<B, 512>>>(lengths, out);
}